// round 15
// baseline (speedup 1.0000x reference)
#include <cuda_runtime.h>
#include <cuda_fp16.h>

#define B_   2
#define S_   2048
#define D_   1024
#define H_   16
#define DK_  64
#define BS_  (B_*S_)            // 4096
#define NBH_ (B_*H_)            // 32

// ---------------- device scratch (no allocations allowed) -------------------
__device__ __half g_x1[BS_ * D_];                         // x fp16 (A)
__device__ __half g_w3[3 * D_ * D_];                      // wq|wk|wv (B)
__device__ __half g_wo[D_ * D_];                          // wo (B)
__device__ __half g_q1[NBH_ * S_ * DK_];                  // Q/8 fp16 (A)
__device__ __half g_k1[NBH_ * S_ * DK_];                  // K fp16 (B)
__device__ __half g_vt[NBH_ * DK_ * S_];                  // V^T fp16 (B) [bh][d][s]
__device__ __half g_cp0[BS_ * D_], g_cp1[BS_ * D_];       // ctx fp16 split-K partials
__device__ float g_rsum_part[64][NBH_ * S_];              // deterministic partials
__device__ float g_inv[NBH_ * S_];                        // 1/rowsum
__device__ float g_attn_fb[(size_t)NBH_ * S_ * S_];       // fallback

// ---------------- smem layouts --------------------------------------------------
// wide GEMM stage (qkv/scores): A 128x64 (16K) + B 128x64 (16K) = 32K
#define ST2_A 0
#define ST2_B 16384
#define ST2_BYTES 32768
// pv_fused: Q 16K | 3x(K 8K + V 8K) | P 16K  = 80K
#define PV_Q      0
#define PV_KV(s)  (16384 + (s) * 16384)
#define PV_P      65536
#define PV_SMEM   81920
// oproj: A 2x16K | B 3x8K = 56K
#define OP_A(s)   ((s) * 16384)
#define OP_B(s)   (32768 + (s) * 8192)
#define OP_SMEM   57344

// ---------------- helpers ----------------------------------------------------
__device__ __forceinline__ unsigned smem_u32(const void* p) {
    return (unsigned)__cvta_generic_to_shared(p);
}
__device__ __forceinline__ void ldsm4(unsigned r[4], unsigned addr) {
    asm volatile("ldmatrix.sync.aligned.m8n8.x4.shared.b16 {%0,%1,%2,%3}, [%4];\n"
                 : "=r"(r[0]), "=r"(r[1]), "=r"(r[2]), "=r"(r[3]) : "r"(addr));
}
__device__ __forceinline__ void mma16816h(float (&d)[4], const unsigned a[4],
                                          unsigned b0, unsigned b1) {
    asm volatile(
        "mma.sync.aligned.m16n8k16.row.col.f32.f16.f16.f32 "
        "{%0,%1,%2,%3}, {%4,%5,%6,%7}, {%8,%9}, {%0,%1,%2,%3};\n"
        : "+f"(d[0]), "+f"(d[1]), "+f"(d[2]), "+f"(d[3])
        : "r"(a[0]), "r"(a[1]), "r"(a[2]), "r"(a[3]), "r"(b0), "r"(b1));
}
__device__ __forceinline__ unsigned pack_h2(float x, float y) {
    __half2 hv = __floats2half2_rn(x, y);
    return *reinterpret_cast<unsigned*>(&hv);
}
__device__ __forceinline__ unsigned hadd2u(unsigned a, unsigned b) {
    __half2 r = __hadd2(*reinterpret_cast<__half2*>(&a),
                        *reinterpret_cast<__half2*>(&b));
    return *reinterpret_cast<unsigned*>(&r);
}
__device__ __forceinline__ unsigned swz(int row, int kb) {
    return (unsigned)(row * 128 + (kb ^ ((row & 7) << 4)));
}
__device__ __forceinline__ void cp16(unsigned dst, const void* src) {
    asm volatile("cp.async.cg.shared.global [%0], [%1], 16;\n" :: "r"(dst), "l"(src));
}
#define CP_COMMIT asm volatile("cp.async.commit_group;\n" ::: "memory")
#define CP_WAIT1  asm volatile("cp.async.wait_group 1;\n" ::: "memory")
#define CP_WAIT0  asm volatile("cp.async.wait_group 0;\n" ::: "memory")

// generic tile stage: NITER*256 cp16 ops, rows of 64 fp16 (128B, swizzled)
template <int NITER>
__device__ __forceinline__ void cp_tile(unsigned Tb,
    const __half* __restrict__ Tp, int ld, int r0, int k0, int tid)
{
#pragma unroll
    for (int j = 0; j < NITER; j++) {
        int id = tid + j * 256, row = id >> 3, c = id & 7;
        size_t g = (size_t)(r0 + row) * ld + k0 + c * 8;
        cp16(Tb + swz(row, c * 16), Tp + g);
    }
}

// ---------------- compute: warp 32x32 (pv/oproj) -------------------------------
__device__ __forceinline__ void compute_stage1(unsigned aBase, unsigned bBase,
                                               int wm, int wn, int lane,
                                               float acc[2][4][4])
{
    const int arow0 = wm * 32 + (lane & 15);
    const int akh   = ((lane >> 4) & 1) * 16;
    const int brow0 = wn * 32 + ((lane >> 4) & 1) * 8 + (lane & 7);
    const int bkh   = ((lane >> 3) & 1) * 16;
#pragma unroll
    for (int ks = 0; ks < 4; ks++) {
        unsigned am[2][4], bm[2][4];
#pragma unroll
        for (int mt = 0; mt < 2; mt++)
            ldsm4(am[mt], aBase + swz(arow0 + mt * 16, ks * 32 + akh));
#pragma unroll
        for (int p = 0; p < 2; p++)
            ldsm4(bm[p], bBase + swz(brow0 + p * 16, ks * 32 + bkh));
#pragma unroll
        for (int mt = 0; mt < 2; mt++)
#pragma unroll
            for (int nt = 0; nt < 4; nt++)
                mma16816h(acc[mt][nt], am[mt],
                          bm[nt >> 1][(nt & 1) * 2], bm[nt >> 1][(nt & 1) * 2 + 1]);
    }
}

// ---------------- compute: warp 64x32, block 128x128 (qkv/scores) --------------
__device__ __forceinline__ void compute_stage2(unsigned aBase, unsigned bBase,
                                               int wm, int wn, int lane,
                                               float acc[4][4][4])
{
    const int arow0 = wm * 64 + (lane & 15);
    const int akh   = ((lane >> 4) & 1) * 16;
    const int brow0 = wn * 32 + ((lane >> 4) & 1) * 8 + (lane & 7);
    const int bkh   = ((lane >> 3) & 1) * 16;
#pragma unroll
    for (int ks = 0; ks < 4; ks++) {
        unsigned am[4][4], bm[2][4];
#pragma unroll
        for (int mt = 0; mt < 4; mt++)
            ldsm4(am[mt], aBase + swz(arow0 + mt * 16, ks * 32 + akh));
#pragma unroll
        for (int p = 0; p < 2; p++)
            ldsm4(bm[p], bBase + swz(brow0 + p * 16, ks * 32 + bkh));
#pragma unroll
        for (int mt = 0; mt < 4; mt++)
#pragma unroll
            for (int nt = 0; nt < 4; nt++)
                mma16816h(acc[mt][nt], am[mt],
                          bm[nt >> 1][(nt & 1) * 2], bm[nt >> 1][(nt & 1) * 2 + 1]);
    }
}

// ---------------- prep: fp32 -> fp16 casts --------------------------------------
__global__ void prep_kernel(const float* __restrict__ x,
                            const float* __restrict__ wq,
                            const float* __restrict__ wk,
                            const float* __restrict__ wv,
                            const float* __restrict__ wo)
{
    const int bid = blockIdx.x, tid = threadIdx.x;
    const float* src;
    __half* dst;
    int base;
    if (bid < 8192)       { src = x;  dst = g_x1;             base = 0;     }
    else if (bid < 10240) { src = wq; dst = g_w3;             base = 8192;  }
    else if (bid < 12288) { src = wk; dst = g_w3 + D_*D_;     base = 10240; }
    else if (bid < 14336) { src = wv; dst = g_w3 + 2*D_*D_;   base = 12288; }
    else                  { src = wo; dst = g_wo;             base = 14336; }
    int i = ((bid - base) * 256 + tid) * 2;
    *reinterpret_cast<unsigned*>(dst + i) = pack_h2(src[i], src[i + 1]);
}

// =============================================================================
// Kernel 1: fused QKV projection — block 128x128, warp 64x32, 3-stage pipeline
// =============================================================================
__global__ __launch_bounds__(256, 2) void qkv_gemm(const float* __restrict__ bq,
                                                   const float* __restrict__ bk,
                                                   const float* __restrict__ bv)
{
    extern __shared__ char sm[];
    const unsigned sb = smem_u32(sm);
    const int m0 = blockIdx.y * 128, n0 = blockIdx.x * 128;
    const int tid = threadIdx.x, lane = tid & 31, wid = tid >> 5;
    const int wm = wid >> 2, wn = wid & 3;
    float acc[4][4][4] = {};

    cp_tile<4>(sb + ST2_A, g_x1, D_, m0, 0, tid);
    cp_tile<4>(sb + ST2_B, g_w3, D_, n0, 0, tid);
    CP_COMMIT;
    cp_tile<4>(sb + ST2_BYTES + ST2_A, g_x1, D_, m0, 64, tid);
    cp_tile<4>(sb + ST2_BYTES + ST2_B, g_w3, D_, n0, 64, tid);
    CP_COMMIT;

    for (int it = 0; it < 16; it++) {
        if (it < 15) { CP_WAIT1; } else { CP_WAIT0; }
        __syncthreads();
        if (it + 2 < 16) {
            const unsigned nb = sb + ((it + 2) % 3) * ST2_BYTES;
            cp_tile<4>(nb + ST2_A, g_x1, D_, m0, (it + 2) * 64, tid);
            cp_tile<4>(nb + ST2_B, g_w3, D_, n0, (it + 2) * 64, tid);
            CP_COMMIT;
        }
        const unsigned cb = sb + (it % 3) * ST2_BYTES;
        compute_stage2(cb + ST2_A, cb + ST2_B, wm, wn, lane, acc);
    }

    const int reg = n0 >> 10;                 // 0=Q,1=K,2=V (n0 mult of 128)
    const float* bp = (reg == 0) ? bq : (reg == 1) ? bk : bv;
    const float scale = (reg == 0) ? 0.125f : 1.0f;
    __half* dQ = (reg == 0) ? g_q1 : g_k1;
    const int tm0 = m0 + wm * 64, tn0 = n0 + wn * 32;

#pragma unroll
    for (int mt = 0; mt < 4; mt++)
#pragma unroll
        for (int nt = 0; nt < 4; nt++) {
            const int c  = tn0 + nt * 8 + 2 * (lane & 3);
            const int h  = (c & 1023) >> 6;
            const int d  = c & 63;
            const float bias0 = bp[c & 1023], bias1 = bp[(c & 1023) + 1];
#pragma unroll
            for (int half = 0; half < 2; half++) {
                const int m = tm0 + mt * 16 + (lane >> 2) + half * 8;
                const float v0 = (acc[mt][nt][half * 2]     + bias0) * scale;
                const float v1 = (acc[mt][nt][half * 2 + 1] + bias1) * scale;
                const int b = m >> 11, s = m & 2047;
                const size_t bh = (size_t)(b * H_ + h);
                if (reg < 2) {
                    size_t idx = (bh * S_ + s) * DK_ + d;
                    *reinterpret_cast<unsigned*>(dQ + idx) = pack_h2(v0, v1);
                } else {
                    size_t i0 = (bh * DK_ + d) * S_ + s;
                    g_vt[i0]      = __float2half(v0);
                    g_vt[i0 + S_] = __float2half(v1);
                }
            }
        }
}

// =============================================================================
// Kernel 2: rowsum partials of exp(QK^T/8) — block 128x128, no P tensor
// =============================================================================
__global__ __launch_bounds__(256, 2) void scores_gemm()
{
    extern __shared__ char sm[];
    const unsigned sb = smem_u32(sm);
    const int bh = blockIdx.z;
    const int m0 = blockIdx.y * 128, n0 = blockIdx.x * 128;
    const int tid = threadIdx.x, lane = tid & 31, wid = tid >> 5;
    const int wm = wid >> 2, wn = wid & 3;

    const __half* Ap = g_q1 + (size_t)bh * S_ * DK_;
    const __half* Bp = g_k1 + (size_t)bh * S_ * DK_;

    float acc[4][4][4] = {};
    cp_tile<4>(sb + ST2_A, Ap, DK_, m0, 0, tid);
    cp_tile<4>(sb + ST2_B, Bp, DK_, n0, 0, tid);
    CP_COMMIT;
    CP_WAIT0;
    __syncthreads();
    compute_stage2(sb + ST2_A, sb + ST2_B, wm, wn, lane, acc);

    const int tm0 = m0 + wm * 64;
    float rpart[4][2] = {};
#pragma unroll
    for (int mt = 0; mt < 4; mt++)
#pragma unroll
        for (int nt = 0; nt < 4; nt++)
#pragma unroll
            for (int half = 0; half < 2; half++) {
                const float e0 = __expf(acc[mt][nt][half * 2]);
                const float e1 = __expf(acc[mt][nt][half * 2 + 1]);
                rpart[mt][half] += e0 + e1;
            }

    const int slot = blockIdx.x * 4 + wn;     // 16 n-tiles x 4 wn = 64 slots
#pragma unroll
    for (int mt = 0; mt < 4; mt++)
#pragma unroll
        for (int half = 0; half < 2; half++) {
            float v = rpart[mt][half];
            v += __shfl_xor_sync(0xffffffffu, v, 1);
            v += __shfl_xor_sync(0xffffffffu, v, 2);
            if ((lane & 3) == 0) {
                const int m = tm0 + mt * 16 + (lane >> 2) + half * 8;
                g_rsum_part[slot][(size_t)bh * S_ + m] = v;
            }
        }
}

// ---------------- inv_kernel: 1/rowsum from 64 partials ------------------------
__global__ void inv_kernel()
{
    const int r = blockIdx.x * 256 + threadIdx.x;   // 65536 rows
    float s = 0.f;
#pragma unroll
    for (int p = 0; p < 64; p++) s += g_rsum_part[p][r];
    g_inv[r] = 1.0f / s;
}

// =============================================================================
// Kernel 3: pv_fused — recompute S, exp, write normalized attn (.cs), P·V
// grid (kz=2, mtile=16, bh=32); 16 n-subtiles of 64, 3-stage K/V pipeline
// =============================================================================
__global__ __launch_bounds__(256, 2) void pv_fused(float* __restrict__ attn_arg)
{
    extern __shared__ char sm[];
    __shared__ float s_inv[128];
    const unsigned sb = smem_u32(sm);
    float* attn = attn_arg ? attn_arg : g_attn_fb;
    const int kz = blockIdx.x, bh = blockIdx.z;
    const int m0 = blockIdx.y * 128;
    const int tid = threadIdx.x, lane = tid & 31, wid = tid >> 5;
    const int wm = wid >> 1, wn = wid & 1;

    if (tid < 128) s_inv[tid] = g_inv[(size_t)bh * S_ + m0 + tid];

    const __half* Qp = g_q1 + (size_t)bh * S_ * DK_;
    const __half* Kp = g_k1 + (size_t)bh * S_ * DK_;
    const __half* Vp = g_vt + (size_t)bh * DK_ * S_;
    float* Aout = attn + (size_t)bh * S_ * S_;

    const int nbase = kz * 1024;

    cp_tile<4>(sb + PV_Q, Qp, DK_, m0, 0, tid);
    cp_tile<2>(sb + PV_KV(0), Kp, DK_, nbase, 0, tid);
    cp_tile<2>(sb + PV_KV(0) + 8192, Vp, S_, 0, nbase, tid);
    CP_COMMIT;
    cp_tile<2>(sb + PV_KV(1), Kp, DK_, nbase + 64, 0, tid);
    cp_tile<2>(sb + PV_KV(1) + 8192, Vp, S_, 0, nbase + 64, tid);
    CP_COMMIT;

    float ctx[2][4][4] = {};

    for (int j = 0; j < 16; j++) {
        const int n0g = nbase + j * 64;
        if (j < 15) { CP_WAIT1; } else { CP_WAIT0; }
        __syncthreads();
        if (j + 2 < 16) {
            const unsigned nb = sb + PV_KV((j + 2) % 3);
            cp_tile<2>(nb, Kp, DK_, n0g + 128, 0, tid);
            cp_tile<2>(nb + 8192, Vp, S_, 0, n0g + 128, tid);
            CP_COMMIT;
        }

        float sacc[2][4][4] = {};
        compute_stage1(sb + PV_Q, sb + PV_KV(j % 3), wm, wn, lane, sacc);

        // exp -> P smem (fp16) + normalized attn (streaming store)
#pragma unroll
        for (int mt = 0; mt < 2; mt++)
#pragma unroll
            for (int nt = 0; nt < 4; nt++)
#pragma unroll
                for (int half = 0; half < 2; half++) {
                    const int rowl = wm * 32 + mt * 16 + (lane >> 2) + half * 8;
                    const int cl = wn * 32 + nt * 8 + 2 * (lane & 3);
                    const float e0 = __expf(sacc[mt][nt][half * 2]);
                    const float e1 = __expf(sacc[mt][nt][half * 2 + 1]);
                    unsigned pk = pack_h2(e0, e1);
                    const unsigned bo = (unsigned)(cl * 2);
                    const unsigned swo = (unsigned)(rowl * 128)
                        + ((bo & 0xFFF0u) ^ (unsigned)((rowl & 7) << 4)) + (bo & 15u);
                    asm volatile("st.shared.b32 [%0], %1;"
                                 :: "r"(sb + PV_P + swo), "r"(pk));
                    __half2 h2 = *reinterpret_cast<__half2*>(&pk);
                    float2 fe = __half22float2(h2);
                    const float inv = s_inv[rowl];
                    float* dp = &Aout[(size_t)(m0 + rowl) * S_ + n0g + cl];
                    asm volatile("st.global.cs.v2.f32 [%0], {%1,%2};"
                                 :: "l"(dp), "f"(fe.x * inv), "f"(fe.y * inv)
                                 : "memory");
                }
        __syncthreads();

        compute_stage1(sb + PV_P, sb + PV_KV(j % 3) + 8192, wm, wn, lane, ctx);
    }

    // epilogue: fp16 partial ctx scaled by inv
    const int b = bh >> 4, h = bh & 15;
    __half* dst = kz ? g_cp1 : g_cp0;
#pragma unroll
    for (int mt = 0; mt < 2; mt++)
#pragma unroll
        for (int nt = 0; nt < 4; nt++) {
            const int c = wn * 32 + nt * 8 + 2 * (lane & 3);
#pragma unroll
            for (int half = 0; half < 2; half++) {
                const int rowl = wm * 32 + mt * 16 + (lane >> 2) + half * 8;
                const float inv = s_inv[rowl];
                const int s = m0 + rowl;
                size_t idx = (size_t)(b * S_ + s) * D_ + h * DK_ + c;
                *reinterpret_cast<unsigned*>(dst + idx) =
                    pack_h2(ctx[mt][nt][half * 2] * inv,
                            ctx[mt][nt][half * 2 + 1] * inv);
            }
        }
}

// =============================================================================
// Kernel 4: out = (cp0 + cp1) @ Wo^T + bo — A summed during staging
// =============================================================================
__global__ __launch_bounds__(256, 2) void oproj_gemm(const float* __restrict__ bo,
                                                     float* __restrict__ out)
{
    extern __shared__ char sm[];
    const unsigned sb = smem_u32(sm);
    const int m0 = blockIdx.y * 128, n0 = blockIdx.x * 64;
    const int tid = threadIdx.x, lane = tid & 31, wid = tid >> 5;
    const int wm = wid >> 1, wn = wid & 1;
    float acc[2][4][4] = {};

    uint4 r0[4], r1[4];
#pragma unroll
    for (int j = 0; j < 4; j++) {
        int id = tid + j * 256, row = id >> 3, c = id & 7;
        size_t g = (size_t)(m0 + row) * D_ + c * 8;
        r0[j] = *reinterpret_cast<const uint4*>(g_cp0 + g);
        r1[j] = *reinterpret_cast<const uint4*>(g_cp1 + g);
    }
    cp_tile<2>(sb + OP_B(0), g_wo, D_, n0, 0, tid);
    CP_COMMIT;
    cp_tile<2>(sb + OP_B(1), g_wo, D_, n0, 64, tid);
    CP_COMMIT;

    for (int it = 0; it < 16; it++) {
        // sum partials, store swizzled
#pragma unroll
        for (int j = 0; j < 4; j++) {
            int id = tid + j * 256, row = id >> 3, c = id & 7;
            unsigned ox = hadd2u(r0[j].x, r1[j].x);
            unsigned oy = hadd2u(r0[j].y, r1[j].y);
            unsigned oz = hadd2u(r0[j].z, r1[j].z);
            unsigned ow = hadd2u(r0[j].w, r1[j].w);
            asm volatile("st.shared.v4.b32 [%0], {%1,%2,%3,%4};"
                         :: "r"(sb + OP_A(it & 1) + swz(row, c * 16)),
                            "r"(ox), "r"(oy), "r"(oz), "r"(ow));
        }
        if (it + 1 < 16) {
#pragma unroll
            for (int j = 0; j < 4; j++) {
                int id = tid + j * 256, row = id >> 3, c = id & 7;
                size_t g = (size_t)(m0 + row) * D_ + (it + 1) * 64 + c * 8;
                r0[j] = *reinterpret_cast<const uint4*>(g_cp0 + g);
                r1[j] = *reinterpret_cast<const uint4*>(g_cp1 + g);
            }
        }
        if (it < 15) { CP_WAIT1; } else { CP_WAIT0; }
        __syncthreads();
        if (it + 2 < 16) {
            cp_tile<2>(sb + OP_B((it + 2) % 3), g_wo, D_, n0, (it + 2) * 64, tid);
            CP_COMMIT;
        }
        compute_stage1(sb + OP_A(it & 1), sb + OP_B(it % 3), wm, wn, lane, acc);
    }

    const int tm0 = m0 + wm * 32, tn0 = n0 + wn * 32;
#pragma unroll
    for (int mt = 0; mt < 2; mt++)
#pragma unroll
        for (int nt = 0; nt < 4; nt++) {
            const int c = tn0 + nt * 8 + 2 * (lane & 3);
            const float b0 = bo[c], b1 = bo[c + 1];
#pragma unroll
            for (int half = 0; half < 2; half++) {
                const int m = tm0 + mt * 16 + (lane >> 2) + half * 8;
                float2 v = { acc[mt][nt][half * 2] + b0,
                             acc[mt][nt][half * 2 + 1] + b1 };
                *reinterpret_cast<float2*>(out + (size_t)m * D_ + c) = v;
            }
        }
}

// =============================================================================
extern "C" void kernel_launch(void* const* d_in, const int* in_sizes, int n_in,
                              void* d_out, int out_size)
{
    const float* x  = (const float*)d_in[0];
    const float* wq = (const float*)d_in[1];
    const float* bq = (const float*)d_in[2];
    const float* wk = (const float*)d_in[3];
    const float* bk = (const float*)d_in[4];
    const float* wv = (const float*)d_in[5];
    const float* bv = (const float*)d_in[6];
    const float* wo = (const float*)d_in[7];
    const float* bo = (const float*)d_in[8];

    float* out = (float*)d_out;
    const long long OUT_E  = (long long)BS_ * D_;
    const long long ATTN_E = (long long)NBH_ * S_ * S_;
    float* attn = ((long long)out_size >= OUT_E + ATTN_E) ? (out + OUT_E) : nullptr;

    static bool attr_done = false;
    if (!attr_done) {
        cudaFuncSetAttribute(qkv_gemm,    cudaFuncAttributeMaxDynamicSharedMemorySize, 3 * ST2_BYTES);
        cudaFuncSetAttribute(pv_fused,    cudaFuncAttributeMaxDynamicSharedMemorySize, PV_SMEM);
        cudaFuncSetAttribute(oproj_gemm,  cudaFuncAttributeMaxDynamicSharedMemorySize, OP_SMEM);
        cudaFuncSetAttribute(scores_gemm, cudaFuncAttributeMaxDynamicSharedMemorySize, ST2_BYTES);
        attr_done = true;
    }

    // 0. precision casts
    prep_kernel<<<16384, 256>>>(x, wq, wk, wv, wo);

    // 1. QKV projection (block 128x128), Q pre-scaled by 1/8
    qkv_gemm<<<dim3(3 * D_ / 128, BS_ / 128), 256, 3 * ST2_BYTES>>>(bq, bk, bv);

    // 2. rowsum partials only (block 128x128, no P tensor)
    scores_gemm<<<dim3(S_ / 128, S_ / 128, NBH_), 256, ST2_BYTES>>>();

    // 3. inverse row sums
    inv_kernel<<<NBH_ * S_ / 256, 256>>>();

    // 4. fused: recompute S, write normalized attn, ctx partials (split-K=2)
    pv_fused<<<dim3(2, S_ / 128, NBH_), 256, PV_SMEM>>>(attn);

    // 5. out projection (sums ctx partials during A staging)
    oproj_gemm<<<dim3(D_ / 64, BS_ / 128), 256, OP_SMEM>>>(bo, out);
}

// round 16
// speedup vs baseline: 1.0500x; 1.0500x over previous
#include <cuda_runtime.h>
#include <cuda_fp16.h>

#define B_   2
#define S_   2048
#define D_   1024
#define H_   16
#define DK_  64
#define BS_  (B_*S_)            // 4096
#define NBH_ (B_*H_)            // 32

// ---------------- device scratch (no allocations allowed) -------------------
__device__ __half g_x1[BS_ * D_];                         // x fp16 (A)
__device__ __half g_w3[3 * D_ * D_];                      // wq|wk|wv (B)
__device__ __half g_wo[D_ * D_];                          // wo (B)
__device__ __half g_q1[NBH_ * S_ * DK_];                  // Q/8 fp16 (A)
__device__ __half g_k1[NBH_ * S_ * DK_];                  // K fp16 (B)
__device__ __half g_vt[NBH_ * DK_ * S_];                  // V^T fp16 (B) [bh][d][s]
__device__ __half g_cp0[BS_ * D_], g_cp1[BS_ * D_];       // ctx fp16 split-K partials
__device__ float g_rsum_part[64][NBH_ * S_];              // deterministic partials
__device__ float g_inv[NBH_ * S_];                        // 1/rowsum
__device__ float g_attn_fb[(size_t)NBH_ * S_ * S_];       // fallback

// ---------------- smem layouts --------------------------------------------------
// single-A GEMM stage: A 16K + B 8K
#define OFF1_A 0
#define OFF1_B 16384
#define STAGE1_BYTES 24576
// pv_fused: Q 16K | 3x(K 8K + V 8K) = 64K  (no P buffer)
#define PV_Q      0
#define PV_KV(s)  (16384 + (s) * 16384)
#define PV_SMEM   65536
// oproj: A 2x16K | B 3x8K = 56K
#define OP_A(s)   ((s) * 16384)
#define OP_B(s)   (32768 + (s) * 8192)
#define OP_SMEM   57344

// ---------------- helpers ----------------------------------------------------
__device__ __forceinline__ unsigned smem_u32(const void* p) {
    return (unsigned)__cvta_generic_to_shared(p);
}
__device__ __forceinline__ void ldsm4(unsigned r[4], unsigned addr) {
    asm volatile("ldmatrix.sync.aligned.m8n8.x4.shared.b16 {%0,%1,%2,%3}, [%4];\n"
                 : "=r"(r[0]), "=r"(r[1]), "=r"(r[2]), "=r"(r[3]) : "r"(addr));
}
__device__ __forceinline__ void mma16816h(float (&d)[4], const unsigned a[4],
                                          unsigned b0, unsigned b1) {
    asm volatile(
        "mma.sync.aligned.m16n8k16.row.col.f32.f16.f16.f32 "
        "{%0,%1,%2,%3}, {%4,%5,%6,%7}, {%8,%9}, {%0,%1,%2,%3};\n"
        : "+f"(d[0]), "+f"(d[1]), "+f"(d[2]), "+f"(d[3])
        : "r"(a[0]), "r"(a[1]), "r"(a[2]), "r"(a[3]), "r"(b0), "r"(b1));
}
__device__ __forceinline__ unsigned pack_h2(float x, float y) {
    __half2 hv = __floats2half2_rn(x, y);
    return *reinterpret_cast<unsigned*>(&hv);
}
__device__ __forceinline__ unsigned hadd2u(unsigned a, unsigned b) {
    __half2 r = __hadd2(*reinterpret_cast<__half2*>(&a),
                        *reinterpret_cast<__half2*>(&b));
    return *reinterpret_cast<unsigned*>(&r);
}
__device__ __forceinline__ unsigned swz(int row, int kb) {
    return (unsigned)(row * 128 + (kb ^ ((row & 7) << 4)));
}
__device__ __forceinline__ void cp16(unsigned dst, const void* src) {
    asm volatile("cp.async.cg.shared.global [%0], [%1], 16;\n" :: "r"(dst), "l"(src));
}
#define CP_COMMIT asm volatile("cp.async.commit_group;\n" ::: "memory")
#define CP_WAIT1  asm volatile("cp.async.wait_group 1;\n" ::: "memory")
#define CP_WAIT0  asm volatile("cp.async.wait_group 0;\n" ::: "memory")

// generic tile stage: NITER*256 cp16 ops, rows of 64 fp16 (128B, swizzled)
template <int NITER>
__device__ __forceinline__ void cp_tile(unsigned Tb,
    const __half* __restrict__ Tp, int ld, int r0, int k0, int tid)
{
#pragma unroll
    for (int j = 0; j < NITER; j++) {
        int id = tid + j * 256, row = id >> 3, c = id & 7;
        size_t g = (size_t)(r0 + row) * ld + k0 + c * 8;
        cp16(Tb + swz(row, c * 16), Tp + g);
    }
}

// ---------------- compute: warp 32x32 (qkv/scores/oproj) -----------------------
__device__ __forceinline__ void compute_stage1(unsigned aBase, unsigned bBase,
                                               int wm, int wn, int lane,
                                               float acc[2][4][4])
{
    const int arow0 = wm * 32 + (lane & 15);
    const int akh   = ((lane >> 4) & 1) * 16;
    const int brow0 = wn * 32 + ((lane >> 4) & 1) * 8 + (lane & 7);
    const int bkh   = ((lane >> 3) & 1) * 16;
#pragma unroll
    for (int ks = 0; ks < 4; ks++) {
        unsigned am[2][4], bm[2][4];
#pragma unroll
        for (int mt = 0; mt < 2; mt++)
            ldsm4(am[mt], aBase + swz(arow0 + mt * 16, ks * 32 + akh));
#pragma unroll
        for (int p = 0; p < 2; p++)
            ldsm4(bm[p], bBase + swz(brow0 + p * 16, ks * 32 + bkh));
#pragma unroll
        for (int mt = 0; mt < 2; mt++)
#pragma unroll
            for (int nt = 0; nt < 4; nt++)
                mma16816h(acc[mt][nt], am[mt],
                          bm[nt >> 1][(nt & 1) * 2], bm[nt >> 1][(nt & 1) * 2 + 1]);
    }
}

// ---------------- prep: fp32 -> fp16 casts --------------------------------------
__global__ void prep_kernel(const float* __restrict__ x,
                            const float* __restrict__ wq,
                            const float* __restrict__ wk,
                            const float* __restrict__ wv,
                            const float* __restrict__ wo)
{
    const int bid = blockIdx.x, tid = threadIdx.x;
    const float* src;
    __half* dst;
    int base;
    if (bid < 8192)       { src = x;  dst = g_x1;             base = 0;     }
    else if (bid < 10240) { src = wq; dst = g_w3;             base = 8192;  }
    else if (bid < 12288) { src = wk; dst = g_w3 + D_*D_;     base = 10240; }
    else if (bid < 14336) { src = wv; dst = g_w3 + 2*D_*D_;   base = 12288; }
    else                  { src = wo; dst = g_wo;             base = 14336; }
    int i = ((bid - base) * 256 + tid) * 2;
    *reinterpret_cast<unsigned*>(dst + i) = pack_h2(src[i], src[i + 1]);
}

// =============================================================================
// Kernel 1: fused QKV projection (single-A, 3-stage pipeline)
// =============================================================================
__global__ __launch_bounds__(256, 2) void qkv_gemm(const float* __restrict__ bq,
                                                   const float* __restrict__ bk,
                                                   const float* __restrict__ bv)
{
    extern __shared__ char sm[];
    const unsigned sb = smem_u32(sm);
    const int m0 = blockIdx.y * 128, n0 = blockIdx.x * 64;
    const int tid = threadIdx.x, lane = tid & 31, wid = tid >> 5;
    const int wm = wid >> 1, wn = wid & 1;
    float acc[2][4][4] = {};

    cp_tile<4>(sb + OFF1_A, g_x1, D_, m0, 0, tid);
    cp_tile<2>(sb + OFF1_B, g_w3, D_, n0, 0, tid);
    CP_COMMIT;
    cp_tile<4>(sb + STAGE1_BYTES + OFF1_A, g_x1, D_, m0, 64, tid);
    cp_tile<2>(sb + STAGE1_BYTES + OFF1_B, g_w3, D_, n0, 64, tid);
    CP_COMMIT;

    for (int it = 0; it < 16; it++) {
        if (it < 15) { CP_WAIT1; } else { CP_WAIT0; }
        __syncthreads();
        if (it + 2 < 16) {
            const unsigned nb = sb + ((it + 2) % 3) * STAGE1_BYTES;
            cp_tile<4>(nb + OFF1_A, g_x1, D_, m0, (it + 2) * 64, tid);
            cp_tile<2>(nb + OFF1_B, g_w3, D_, n0, (it + 2) * 64, tid);
            CP_COMMIT;
        }
        const unsigned cb = sb + (it % 3) * STAGE1_BYTES;
        compute_stage1(cb + OFF1_A, cb + OFF1_B, wm, wn, lane, acc);
    }

    const int reg = n0 >> 10;                 // 0=Q,1=K,2=V
    const int h   = (n0 & 1023) >> 6;
    const float* bp = (reg == 0) ? bq : (reg == 1) ? bk : bv;
    const float scale = (reg == 0) ? 0.125f : 1.0f;
    __half* dQ = (reg == 0) ? g_q1 : g_k1;
    const int tm0 = m0 + wm * 32, tn0 = n0 + wn * 32;

#pragma unroll
    for (int mt = 0; mt < 2; mt++)
#pragma unroll
        for (int nt = 0; nt < 4; nt++) {
            const int c  = tn0 + nt * 8 + 2 * (lane & 3);
            const int d  = c & 63;
            const float bias0 = bp[c & 1023], bias1 = bp[(c & 1023) + 1];
#pragma unroll
            for (int half = 0; half < 2; half++) {
                const int m = tm0 + mt * 16 + (lane >> 2) + half * 8;
                const float v0 = (acc[mt][nt][half * 2]     + bias0) * scale;
                const float v1 = (acc[mt][nt][half * 2 + 1] + bias1) * scale;
                const int b = m >> 11, s = m & 2047;
                const size_t bh = (size_t)(b * H_ + h);
                if (reg < 2) {
                    size_t idx = (bh * S_ + s) * DK_ + d;
                    *reinterpret_cast<unsigned*>(dQ + idx) = pack_h2(v0, v1);
                } else {
                    size_t i0 = (bh * DK_ + d) * S_ + s;
                    g_vt[i0]      = __float2half(v0);
                    g_vt[i0 + S_] = __float2half(v1);
                }
            }
        }
}

// =============================================================================
// Kernel 2: rowsum partials of exp(QK^T/8) — NO P materialization
// =============================================================================
__global__ __launch_bounds__(256) void scores_gemm()
{
    extern __shared__ char sm[];
    const unsigned sb = smem_u32(sm);
    const int bh = blockIdx.z;
    const int m0 = blockIdx.y * 128, n0 = blockIdx.x * 64;
    const int tid = threadIdx.x, lane = tid & 31, wid = tid >> 5;
    const int wm = wid >> 1, wn = wid & 1;

    const __half* Ap = g_q1 + (size_t)bh * S_ * DK_;
    const __half* Bp = g_k1 + (size_t)bh * S_ * DK_;

    float acc[2][4][4] = {};
    cp_tile<4>(sb + OFF1_A, Ap, DK_, m0, 0, tid);
    cp_tile<2>(sb + OFF1_B, Bp, DK_, n0, 0, tid);
    CP_COMMIT;
    CP_WAIT0;
    __syncthreads();
    compute_stage1(sb + OFF1_A, sb + OFF1_B, wm, wn, lane, acc);

    const int tm0 = m0 + wm * 32;
    float rpart[2][2] = {};
#pragma unroll
    for (int mt = 0; mt < 2; mt++)
#pragma unroll
        for (int nt = 0; nt < 4; nt++)
#pragma unroll
            for (int half = 0; half < 2; half++) {
                const float e0 = __expf(acc[mt][nt][half * 2]);
                const float e1 = __expf(acc[mt][nt][half * 2 + 1]);
                rpart[mt][half] += e0 + e1;
            }

    const int slot = blockIdx.x * 2 + wn;
#pragma unroll
    for (int mt = 0; mt < 2; mt++)
#pragma unroll
        for (int half = 0; half < 2; half++) {
            float v = rpart[mt][half];
            v += __shfl_xor_sync(0xffffffffu, v, 1);
            v += __shfl_xor_sync(0xffffffffu, v, 2);
            if ((lane & 3) == 0) {
                const int m = tm0 + mt * 16 + (lane >> 2) + half * 8;
                g_rsum_part[slot][(size_t)bh * S_ + m] = v;
            }
        }
}

// ---------------- inv_kernel: 1/rowsum from 64 partials ------------------------
__global__ void inv_kernel()
{
    const int r = blockIdx.x * 256 + threadIdx.x;   // 65536 rows
    float s = 0.f;
#pragma unroll
    for (int p = 0; p < 64; p++) s += g_rsum_part[p][r];
    g_inv[r] = 1.0f / s;
}

// =============================================================================
// Kernel 3: pv_fused — warps split m only (16 rows each); P stays in registers
// grid (kz=2, mtile=16, bh=32); 16 n-subtiles of 64; ONE sync per iteration
// =============================================================================
__global__ __launch_bounds__(256, 2) void pv_fused(float* __restrict__ attn_arg)
{
    extern __shared__ char sm[];
    __shared__ float s_inv[128];
    const unsigned sb = smem_u32(sm);
    float* attn = attn_arg ? attn_arg : g_attn_fb;
    const int kz = blockIdx.x, bh = blockIdx.z;
    const int m0 = blockIdx.y * 128;
    const int tid = threadIdx.x, lane = tid & 31, wid = tid >> 5;

    if (tid < 128) s_inv[tid] = g_inv[(size_t)bh * S_ + m0 + tid];

    const __half* Qp = g_q1 + (size_t)bh * S_ * DK_;
    const __half* Kp = g_k1 + (size_t)bh * S_ * DK_;
    const __half* Vp = g_vt + (size_t)bh * DK_ * S_;
    float* Aout = attn + (size_t)bh * S_ * S_;

    const int nbase = kz * 1024;

    cp_tile<4>(sb + PV_Q, Qp, DK_, m0, 0, tid);
    cp_tile<2>(sb + PV_KV(0), Kp, DK_, nbase, 0, tid);
    cp_tile<2>(sb + PV_KV(0) + 8192, Vp, S_, 0, nbase, tid);
    CP_COMMIT;
    cp_tile<2>(sb + PV_KV(1), Kp, DK_, nbase + 64, 0, tid);
    cp_tile<2>(sb + PV_KV(1) + 8192, Vp, S_, 0, nbase + 64, tid);
    CP_COMMIT;

    // warp-private fragment geometry
    const int arow   = wid * 16 + (lane & 15);
    const int akh    = ((lane >> 4) & 1) * 16;
    const int brow   = ((lane >> 4) & 1) * 8 + (lane & 7);
    const int bkh    = ((lane >> 3) & 1) * 16;
    const int r0l    = wid * 16 + (lane >> 2);      // local row of c0/c1
    const float inv0 = 0.f;                          // (placeholder, set below)
    (void)inv0;

    float ctx[8][4] = {};

    for (int j = 0; j < 16; j++) {
        const int n0g = nbase + j * 64;
        if (j < 15) { CP_WAIT1; } else { CP_WAIT0; }
        __syncthreads();   // KV(j) ready; all warps past MMAs of j-1
        if (j + 2 < 16) {
            const unsigned nb = sb + PV_KV((j + 2) % 3);
            cp_tile<2>(nb, Kp, DK_, n0g + 128, 0, tid);
            cp_tile<2>(nb + 8192, Vp, S_, 0, n0g + 128, tid);
            CP_COMMIT;
        }

        // ---- S = (Q/8)·K^T : warp tile 16 x 64 -----------------------------
        float sacc[8][4] = {};
        const unsigned kb = sb + PV_KV(j % 3);
#pragma unroll
        for (int ks = 0; ks < 4; ks++) {
            unsigned am[4], bm[4][4];
            ldsm4(am, sb + PV_Q + swz(arow, ks * 32 + akh));
#pragma unroll
            for (int p = 0; p < 4; p++)
                ldsm4(bm[p], kb + swz(p * 16 + brow, ks * 32 + bkh));
#pragma unroll
            for (int nt = 0; nt < 8; nt++)
                mma16816h(sacc[nt], am,
                          bm[nt >> 1][(nt & 1) * 2], bm[nt >> 1][(nt & 1) * 2 + 1]);
        }

        // ---- exp -> register P A-frags + normalized attn write -------------
        unsigned pa[4][4];
        const float invA = s_inv[r0l];
        const float invB = s_inv[r0l + 8];
#pragma unroll
        for (int nt = 0; nt < 8; nt++) {
            const float e0 = __expf(sacc[nt][0]);
            const float e1 = __expf(sacc[nt][1]);
            const float e2 = __expf(sacc[nt][2]);
            const float e3 = __expf(sacc[nt][3]);
            unsigned p01 = pack_h2(e0, e1);
            unsigned p23 = pack_h2(e2, e3);
            pa[nt >> 1][(nt & 1) * 2]     = p01;
            pa[nt >> 1][(nt & 1) * 2 + 1] = p23;
            const int cl = n0g + nt * 8 + 2 * (lane & 3);
            float2 fA = __half22float2(*reinterpret_cast<__half2*>(&p01));
            float2 fB = __half22float2(*reinterpret_cast<__half2*>(&p23));
            float* dpA = &Aout[(size_t)(m0 + r0l) * S_ + cl];
            float* dpB = &Aout[(size_t)(m0 + r0l + 8) * S_ + cl];
            asm volatile("st.global.cs.v2.f32 [%0], {%1,%2};"
                         :: "l"(dpA), "f"(fA.x * invA), "f"(fA.y * invA) : "memory");
            asm volatile("st.global.cs.v2.f32 [%0], {%1,%2};"
                         :: "l"(dpB), "f"(fB.x * invB), "f"(fB.y * invB) : "memory");
        }

        // ---- ctx += P · V : A from registers, B = V^T tile ------------------
        const unsigned vb = sb + PV_KV(j % 3) + 8192;
#pragma unroll
        for (int kt = 0; kt < 4; kt++) {
            unsigned bm[4][4];
#pragma unroll
            for (int p = 0; p < 4; p++)
                ldsm4(bm[p], vb + swz(p * 16 + brow, kt * 32 + bkh));
#pragma unroll
            for (int dt = 0; dt < 8; dt++)
                mma16816h(ctx[dt], pa[kt],
                          bm[dt >> 1][(dt & 1) * 2], bm[dt >> 1][(dt & 1) * 2 + 1]);
        }
    }

    // epilogue: fp16 partial ctx scaled by inv
    const int b = bh >> 4, h = bh & 15;
    __half* dst = kz ? g_cp1 : g_cp0;
    const float invA = s_inv[r0l];
    const float invB = s_inv[r0l + 8];
#pragma unroll
    for (int dt = 0; dt < 8; dt++) {
        const int c = dt * 8 + 2 * (lane & 3);
        size_t iA = (size_t)(b * S_ + m0 + r0l) * D_ + h * DK_ + c;
        size_t iB = (size_t)(b * S_ + m0 + r0l + 8) * D_ + h * DK_ + c;
        *reinterpret_cast<unsigned*>(dst + iA) =
            pack_h2(ctx[dt][0] * invA, ctx[dt][1] * invA);
        *reinterpret_cast<unsigned*>(dst + iB) =
            pack_h2(ctx[dt][2] * invB, ctx[dt][3] * invB);
    }
}

// =============================================================================
// Kernel 4: out = (cp0 + cp1) @ Wo^T + bo — A summed during staging
// =============================================================================
__global__ __launch_bounds__(256, 2) void oproj_gemm(const float* __restrict__ bo,
                                                     float* __restrict__ out)
{
    extern __shared__ char sm[];
    const unsigned sb = smem_u32(sm);
    const int m0 = blockIdx.y * 128, n0 = blockIdx.x * 64;
    const int tid = threadIdx.x, lane = tid & 31, wid = tid >> 5;
    const int wm = wid >> 1, wn = wid & 1;
    float acc[2][4][4] = {};

    uint4 r0[4], r1[4];
#pragma unroll
    for (int j = 0; j < 4; j++) {
        int id = tid + j * 256, row = id >> 3, c = id & 7;
        size_t g = (size_t)(m0 + row) * D_ + c * 8;
        r0[j] = *reinterpret_cast<const uint4*>(g_cp0 + g);
        r1[j] = *reinterpret_cast<const uint4*>(g_cp1 + g);
    }
    cp_tile<2>(sb + OP_B(0), g_wo, D_, n0, 0, tid);
    CP_COMMIT;
    cp_tile<2>(sb + OP_B(1), g_wo, D_, n0, 64, tid);
    CP_COMMIT;

    for (int it = 0; it < 16; it++) {
#pragma unroll
        for (int j = 0; j < 4; j++) {
            int id = tid + j * 256, row = id >> 3, c = id & 7;
            unsigned ox = hadd2u(r0[j].x, r1[j].x);
            unsigned oy = hadd2u(r0[j].y, r1[j].y);
            unsigned oz = hadd2u(r0[j].z, r1[j].z);
            unsigned ow = hadd2u(r0[j].w, r1[j].w);
            asm volatile("st.shared.v4.b32 [%0], {%1,%2,%3,%4};"
                         :: "r"(sb + OP_A(it & 1) + swz(row, c * 16)),
                            "r"(ox), "r"(oy), "r"(oz), "r"(ow));
        }
        if (it + 1 < 16) {
#pragma unroll
            for (int j = 0; j < 4; j++) {
                int id = tid + j * 256, row = id >> 3, c = id & 7;
                size_t g = (size_t)(m0 + row) * D_ + (it + 1) * 64 + c * 8;
                r0[j] = *reinterpret_cast<const uint4*>(g_cp0 + g);
                r1[j] = *reinterpret_cast<const uint4*>(g_cp1 + g);
            }
        }
        if (it < 15) { CP_WAIT1; } else { CP_WAIT0; }
        __syncthreads();
        if (it + 2 < 16) {
            cp_tile<2>(sb + OP_B((it + 2) % 3), g_wo, D_, n0, (it + 2) * 64, tid);
            CP_COMMIT;
        }
        compute_stage1(sb + OP_A(it & 1), sb + OP_B(it % 3), wm, wn, lane, acc);
    }

    const int tm0 = m0 + wm * 32, tn0 = n0 + wn * 32;
#pragma unroll
    for (int mt = 0; mt < 2; mt++)
#pragma unroll
        for (int nt = 0; nt < 4; nt++) {
            const int c = tn0 + nt * 8 + 2 * (lane & 3);
            const float b0 = bo[c], b1 = bo[c + 1];
#pragma unroll
            for (int half = 0; half < 2; half++) {
                const int m = tm0 + mt * 16 + (lane >> 2) + half * 8;
                float2 v = { acc[mt][nt][half * 2] + b0,
                             acc[mt][nt][half * 2 + 1] + b1 };
                *reinterpret_cast<float2*>(out + (size_t)m * D_ + c) = v;
            }
        }
}

// =============================================================================
extern "C" void kernel_launch(void* const* d_in, const int* in_sizes, int n_in,
                              void* d_out, int out_size)
{
    const float* x  = (const float*)d_in[0];
    const float* wq = (const float*)d_in[1];
    const float* bq = (const float*)d_in[2];
    const float* wk = (const float*)d_in[3];
    const float* bk = (const float*)d_in[4];
    const float* wv = (const float*)d_in[5];
    const float* bv = (const float*)d_in[6];
    const float* wo = (const float*)d_in[7];
    const float* bo = (const float*)d_in[8];

    float* out = (float*)d_out;
    const long long OUT_E  = (long long)BS_ * D_;
    const long long ATTN_E = (long long)NBH_ * S_ * S_;
    float* attn = ((long long)out_size >= OUT_E + ATTN_E) ? (out + OUT_E) : nullptr;

    static bool attr_done = false;
    if (!attr_done) {
        cudaFuncSetAttribute(qkv_gemm,    cudaFuncAttributeMaxDynamicSharedMemorySize, 3 * STAGE1_BYTES);
        cudaFuncSetAttribute(pv_fused,    cudaFuncAttributeMaxDynamicSharedMemorySize, PV_SMEM);
        cudaFuncSetAttribute(oproj_gemm,  cudaFuncAttributeMaxDynamicSharedMemorySize, OP_SMEM);
        cudaFuncSetAttribute(scores_gemm, cudaFuncAttributeMaxDynamicSharedMemorySize, STAGE1_BYTES);
        attr_done = true;
    }

    // 0. precision casts
    prep_kernel<<<16384, 256>>>(x, wq, wk, wv, wo);

    // 1. QKV projection (single-A), Q pre-scaled by 1/8
    qkv_gemm<<<dim3(3 * D_ / 64, BS_ / 128), 256, 3 * STAGE1_BYTES>>>(bq, bk, bv);

    // 2. rowsum partials only (no P tensor)
    scores_gemm<<<dim3(S_ / 64, S_ / 128, NBH_), 256, STAGE1_BYTES>>>();

    // 3. inverse row sums
    inv_kernel<<<NBH_ * S_ / 256, 256>>>();

    // 4. fused: recompute S, register-resident P, normalized attn, ctx partials
    pv_fused<<<dim3(2, S_ / 128, NBH_), 256, PV_SMEM>>>(attn);

    // 5. out projection (sums ctx partials during A staging)
    oproj_gemm<<<dim3(D_ / 64, BS_ / 128), 256, OP_SMEM>>>(bo, out);
}